// round 11
// baseline (speedup 1.0000x reference)
#include <cuda_runtime.h>
#include <cuda_fp16.h>
#include <cstdint>

// ---------------- problem constants ----------------
#define NB 256     // batch
#define NT 256     // timesteps
#define D_T 300
#define D_A 74
#define D_V 35
#define DD 409
#define KP 448     // padded D (multiple of 64)
#define NH 1024    // hidden
#define KF (KP + NH)   // fused K = 1472
#define NG 4096    // 4*H
#define NC 512     // MLP cell

#define NCTA_REC 128
#define BPITCH 1480            // halves; 740 words ≡ 4 (mod 32) -> conflict-free B frags
#define APITCH 72              // halves; 36 words ≡ 4 (mod 32) -> conflict-free A frags
#define ASTAGE (128 * APITCH)  // halves per A stage
#define NASTG 2
#define NITER (KF / 64)        // 23 chunks of 64 halves
#define NXCH (KP / 64)         // 7 x-chunks
#define REC_SMEM (NASTG * ASTAGE * 2 + 64 * BPITCH * 2)   // 36864 + 189440 = 226304 B

// ---------------- device scratch (no allocs allowed) ----------------
__device__ __half g_Xh[(size_t)NB * NT * KP];       // 58.7 MB fp16, row = t*NB+b
__device__ __half g_Wf[(size_t)NG * KF];            // fused [W_ih(448 pad) | W_hh(1024)] fp16
__device__ float  g_bias[NG];                       // b_ih + b_hh
__device__ __half g_hbuf[2][NB * NH];               // double-buffered h (fp16)
__device__ float  g_hidden[NB * NC];
__device__ unsigned g_bar_arrive;
__device__ unsigned g_bar_gen;

// ---------------- helpers ----------------
__device__ __forceinline__ void mma16(float* c, uint32_t a0, uint32_t a1, uint32_t a2,
                                      uint32_t a3, uint32_t b0, uint32_t b1) {
    asm("mma.sync.aligned.m16n8k16.row.col.f32.f16.f16.f32 "
        "{%0,%1,%2,%3}, {%4,%5,%6,%7}, {%8,%9}, {%0,%1,%2,%3};\n"
        : "+f"(c[0]), "+f"(c[1]), "+f"(c[2]), "+f"(c[3])
        : "r"(a0), "r"(a1), "r"(a2), "r"(a3), "r"(b0), "r"(b1));
}

__device__ __forceinline__ float fast_sig(float x) {
    return __fdividef(1.f, 1.f + __expf(-x));
}
__device__ __forceinline__ float fast_tanh(float x) {
    return 1.f - __fdividef(2.f, __expf(2.f * x) + 1.f);
}

__device__ __forceinline__ uint32_t smem_u32(const void* p) {
    uint32_t a;
    asm("{ .reg .u64 t; cvta.to.shared.u64 t, %1; cvt.u32.u64 %0, t; }" : "=r"(a) : "l"(p));
    return a;
}

// ---------------- packing / init ----------------
__global__ void pack_x(const float* __restrict__ xt, const float* __restrict__ xa,
                       const float* __restrict__ xv) {
    size_t idx = (size_t)blockIdx.x * blockDim.x + threadIdx.x;
    int d = (int)(idx % KP);
    size_t r = idx / KP;             // r = t*NB + b
    int t = (int)(r / NB), b = (int)(r % NB);
    float v = 0.f;
    if (d < D_T)            v = xt[((size_t)b * NT + t) * D_T + d];
    else if (d < D_T + D_A) v = xa[((size_t)b * NT + t) * D_A + (d - D_T)];
    else if (d < DD)        v = xv[((size_t)b * NT + t) * D_V + (d - D_T - D_A)];
    g_Xh[idx] = __float2half(v);
}

// fused weight: row g (0..4095): [W_ih[g][0..408] pad to 448 | W_hh[g][0..1023]]
__global__ void pack_wf(const float* __restrict__ Wih, const float* __restrict__ Whh) {
    size_t idx = (size_t)blockIdx.x * blockDim.x + threadIdx.x;
    int d = (int)(idx % KF);
    size_t row = idx / KF;
    float v;
    if (d < KP) v = (d < DD) ? Wih[row * DD + d] : 0.f;
    else        v = Whh[row * NH + (d - KP)];
    g_Wf[idx] = __float2half(v);
}

__global__ void pack_bias(const float* __restrict__ bih, const float* __restrict__ bhh) {
    int i = blockIdx.x * blockDim.x + threadIdx.x;
    g_bias[i] = bih[i] + bhh[i];
}

__global__ void zero_state() {
    int i = blockIdx.x * blockDim.x + threadIdx.x;
    ((__half*)g_hbuf)[i] = __float2half(0.f);
    if (i == 0) { g_bar_arrive = 0u; g_bar_gen = 0u; }
}

// ---------------- persistent fused LSTM kernel ----------------
// 128 CTAs, 512 threads (16 warps: wm 0..7 x wn 0..1). CTA = 128 batch x 16 h-cols.
// gates = [x_t | h_{t-1}] @ Wf^T + bias, K = 1472 in 23 chunks of 64.
// Wf slice resident in smem (189 KB); c in registers; h double-buffered in gmem;
// 2-stage A pipeline; one grid barrier per step.
__global__ __launch_bounds__(512, 1) void lstm_rec() {
    extern __shared__ __align__(16) __half dsm[];
    __half (*As)[128][APITCH] = (__half (*)[128][APITCH])dsm;          // 2 stages
    __half (*Bs)[BPITCH] = (__half (*)[BPITCH])(dsm + NASTG * ASTAGE);

    const int tid = threadIdx.x;
    const int warp = tid >> 5, lane = tid & 31;
    const int gid = lane >> 2, tig = lane & 3;
    const int wm = warp >> 1;          // 0..7 : 16-row slices
    const int wn = warp & 1;           // 0..1 : 8 h-cols each
    const int blk = blockIdx.x;
    const int nbase = (blk & 63) * 16;     // h-col base
    const int mbase = (blk >> 6) * 128;    // batch base

    // ---- load fused weight slice into smem once (64 rows x 1472 halves) ----
    for (int q = tid; q < 64 * (KF / 8); q += 512) {
        const int j = q / (KF / 8), s = q % (KF / 8);  // j: gate*16+col, s: 8-half seg
        const int gate = j >> 4, col = nbase + (j & 15);
        *(uint4*)(&Bs[j][s * 8]) =
            *(const uint4*)(g_Wf + (size_t)(gate * NH + col) * KF + s * 8);
    }
    __syncthreads();

    // ---- cp.async plan for A: 2 x 16B segments per thread per 64-half chunk ----
    uint32_t dstA[2];
    size_t xoff[2], hoff[2];
#pragma unroll
    for (int i = 0; i < 2; i++) {
        const int seg = tid + 512 * i;                // 0..1023
        const int row = seg >> 3, q = seg & 7;        // 8 segs of 16B per row
        dstA[i] = smem_u32(&As[0][row][q * 8]);
        xoff[i] = (size_t)(mbase + row) * KP + q * 8;
        hoff[i] = (size_t)(mbase + row) * NH + q * 8;
    }
    const uint32_t stA = ASTAGE * 2;   // bytes per A stage

    const int rr0 = wm * 16 + gid;
    const int row0 = mbase + rr0;
    const int nc = nbase + wn * 8 + 2 * tig;

    // bias per thread's output columns (col-only, same for all batch rows)
    float bsv[4][2];
#pragma unroll
    for (int g = 0; g < 4; g++) {
        bsv[g][0] = g_bias[g * NH + nc];
        bsv[g][1] = g_bias[g * NH + nc + 1];
    }

    float creg[4];
#pragma unroll
    for (int p = 0; p < 4; p++) creg[p] = 0.f;

    for (int t = 0; t < NT; t++) {
        const __half* hR = g_hbuf[t & 1];
        __half* hW = g_hbuf[(t + 1) & 1];
        const __half* xT = g_Xh + (size_t)t * NB * KP;

#define CPA(kc_) do {                                                               \
        _Pragma("unroll")                                                           \
        for (int i_ = 0; i_ < 2; i_++) {                                            \
            const __half* s_ = ((kc_) < NXCH)                                       \
                ? (xT + xoff[i_] + (kc_) * 64)                                      \
                : (hR + hoff[i_] + ((kc_) - NXCH) * 64);                            \
            asm volatile("cp.async.cg.shared.global [%0], [%1], 16;\n"              \
                         :: "r"(dstA[i_] + ((kc_) & 1) * stA), "l"(s_));            \
        }                                                                           \
        asm volatile("cp.async.commit_group;\n" ::: "memory");                      \
} while (0)

        CPA(0);

        float acc[4][4];
#pragma unroll
        for (int g = 0; g < 4; g++)
#pragma unroll
            for (int k = 0; k < 4; k++) acc[g][k] = 0.f;

#pragma unroll 1
        for (int kc = 0; kc < NITER; kc++) {
            asm volatile("cp.async.wait_group 0;\n" ::: "memory");
            __syncthreads();
            if (kc + 1 < NITER) CPA(kc + 1);

            const int cur = kc & 1;
#pragma unroll
            for (int s = 0; s < 4; s++) {
                const int ko = s * 16;
                uint32_t a0, a1, a2, a3;
                a0 = *(const uint32_t*)(&As[cur][rr0][ko + 2 * tig]);
                a1 = *(const uint32_t*)(&As[cur][rr0 + 8][ko + 2 * tig]);
                a2 = *(const uint32_t*)(&As[cur][rr0][ko + 2 * tig + 8]);
                a3 = *(const uint32_t*)(&As[cur][rr0 + 8][ko + 2 * tig + 8]);
                const int kg = kc * 64 + ko;
#pragma unroll
                for (int g = 0; g < 4; g++) {
                    const int nb = g * 16 + wn * 8 + gid;
                    const uint32_t b0 = *(const uint32_t*)(&Bs[nb][kg + 2 * tig]);
                    const uint32_t b1 = *(const uint32_t*)(&Bs[nb][kg + 2 * tig + 8]);
                    mma16(acc[g], a0, a1, a2, a3, b0, b1);
                }
            }
            // no trailing sync: next iteration's top barrier orders stage reuse
        }
#undef CPA

        // ---- pointwise LSTM update (all 4 gates thread-local) ----
        {
            float hv[4];
#pragma unroll
            for (int p = 0; p < 4; p++) {
                const int e = p & 1;
                const float iv = fast_sig(acc[0][p] + bsv[0][e]);
                const float fv = fast_sig(acc[1][p] + bsv[1][e]);
                const float gv = fast_tanh(acc[2][p] + bsv[2][e]);
                const float ov = fast_sig(acc[3][p] + bsv[3][e]);
                const float cn = fv * creg[p] + iv * gv;
                creg[p] = cn;
                hv[p] = ov * fast_tanh(cn);
            }
            *(__half2*)(&hW[(size_t)row0 * NH + nc]) = __floats2half2_rn(hv[0], hv[1]);
            *(__half2*)(&hW[(size_t)(row0 + 8) * NH + nc]) = __floats2half2_rn(hv[2], hv[3]);
        }

        // ---- grid-wide barrier (skip after last step) ----
        if (t + 1 < NT) {
            __syncthreads();
            if (tid == 0) {
                __threadfence();
                const unsigned old = atomicAdd(&g_bar_arrive, 1u);
                if (old == NCTA_REC - 1) {
                    g_bar_arrive = 0u;
                    __threadfence();
                    atomicAdd(&g_bar_gen, 1u);
                } else {
                    const unsigned target = (unsigned)(t + 1);
                    while (*((volatile unsigned*)&g_bar_gen) < target) {}
                }
                __threadfence();
            }
            __syncthreads();
        }
    }
}

// ---------------- MLP head ----------------
__global__ void mlp1(const float* __restrict__ W1, const float* __restrict__ b1) {
    const int b = blockIdx.y * 32 + threadIdx.x;
    const int c = blockIdx.x * 8 + threadIdx.y;
    const __half* hr = g_hbuf[0] + (size_t)b * NH;   // final h lands in buffer 0 (NT even)
    const float* wr = W1 + (size_t)c * NH;
    float s = 0.f;
#pragma unroll 4
    for (int k = 0; k < NH; k++) s += __half2float(hr[k]) * wr[k];
    g_hidden[(size_t)b * NC + c] = fmaxf(s + b1[c], 0.f);
}

__global__ void mlp2(const float* __restrict__ W2, const float* __restrict__ b2,
                     float* __restrict__ out) {
    const int b = blockIdx.x;
    const int tid = threadIdx.x;  // 128
    float s = 0.f;
    for (int c = tid; c < NC; c += 128) s += g_hidden[b * NC + c] * W2[c];
#pragma unroll
    for (int o = 16; o > 0; o >>= 1) s += __shfl_down_sync(0xffffffffu, s, o);
    __shared__ float red[4];
    if ((tid & 31) == 0) red[tid >> 5] = s;
    __syncthreads();
    if (tid == 0) out[b] = red[0] + red[1] + red[2] + red[3] + b2[0];
}

// ---------------- launch ----------------
extern "C" void kernel_launch(void* const* d_in, const int* in_sizes, int n_in,
                              void* d_out, int out_size) {
    const float* x_text = (const float*)d_in[0];
    const float* x_audio = (const float*)d_in[1];
    const float* x_vision = (const float*)d_in[2];
    const float* W_ih = (const float*)d_in[3];
    const float* W_hh = (const float*)d_in[4];
    const float* b_ih = (const float*)d_in[5];
    const float* b_hh = (const float*)d_in[6];
    const float* W1 = (const float*)d_in[7];
    const float* b1 = (const float*)d_in[8];
    const float* W2 = (const float*)d_in[9];
    const float* b2 = (const float*)d_in[10];
    float* out = (float*)d_out;

    static int s_attr_done = 0;
    if (!s_attr_done) {
        cudaFuncSetAttribute(lstm_rec, cudaFuncAttributeMaxDynamicSharedMemorySize,
                             REC_SMEM);
        s_attr_done = 1;
    }

    pack_x<<<(int)(((size_t)NB * NT * KP) / 256), 256>>>(x_text, x_audio, x_vision);
    pack_wf<<<(int)(((size_t)NG * KF) / 256), 256>>>(W_ih, W_hh);
    pack_bias<<<NG / 256, 256>>>(b_ih, b_hh);
    zero_state<<<(2 * NB * NH) / 256, 256>>>();

    lstm_rec<<<NCTA_REC, 512, REC_SMEM>>>();

    mlp1<<<dim3(64, 8), dim3(32, 8)>>>(W1, b1);
    mlp2<<<NB, 128>>>(W2, b2, out);
}